// round 1
// baseline (speedup 1.0000x reference)
#include <cuda_runtime.h>

// SNN Leaky (snntorch, reset_mechanism='subtract') forward:
//   reset_t = H(mem_{t-1} - 1)  == spk_{t-1}
//   mem_t   = 0.5*mem_{t-1} + x_t - reset_t
//   spk_t   = H(mem_t - 1)
// x: [T=128, B=64, N=4096] float32 -> spk: [128, 64, 4096] float32
//
// Pure HBM-streaming kernel: 1 thread per float4 of neurons, sequential
// over T with unroll-4 so the independent x loads front-batch (MLP~4).

#define T_STEPS 128
#define BN4 65536  // (64*4096)/4 float4 elements per timestep

__global__ __launch_bounds__(256) void snn_leaky_kernel(
    const float4* __restrict__ x4, float4* __restrict__ o4)
{
    int idx = blockIdx.x * blockDim.x + threadIdx.x;  // 0..BN4-1

    float4 mem = make_float4(0.f, 0.f, 0.f, 0.f);
    float4 spk = make_float4(0.f, 0.f, 0.f, 0.f);

    const float4* xp = x4 + idx;
    float4* op = o4 + idx;

#pragma unroll 4
    for (int t = 0; t < T_STEPS; t++) {
        float4 xt = xp[t * BN4];

        mem.x = 0.5f * mem.x + xt.x - spk.x;
        mem.y = 0.5f * mem.y + xt.y - spk.y;
        mem.z = 0.5f * mem.z + xt.z - spk.z;
        mem.w = 0.5f * mem.w + xt.w - spk.w;

        spk.x = (mem.x > 1.0f) ? 1.0f : 0.0f;
        spk.y = (mem.y > 1.0f) ? 1.0f : 0.0f;
        spk.z = (mem.z > 1.0f) ? 1.0f : 0.0f;
        spk.w = (mem.w > 1.0f) ? 1.0f : 0.0f;

        op[t * BN4] = spk;
    }
}

extern "C" void kernel_launch(void* const* d_in, const int* in_sizes, int n_in,
                              void* d_out, int out_size)
{
    const float4* x4 = (const float4*)d_in[0];
    float4* o4 = (float4*)d_out;
    // BN4 threads total
    snn_leaky_kernel<<<BN4 / 256, 256>>>(x4, o4);
}

// round 2
// speedup vs baseline: 1.0536x; 1.0536x over previous
#include <cuda_runtime.h>

// SNN Leaky forward (reset='subtract'):
//   mem = 0.5*mem + x_t - spk;  spk = (mem > 1) ? 1 : 0
// x: [128, 64, 4096] f32 -> spk same shape. Pure HBM streaming.
//
// R2 changes vs R1 (43us kernel, DRAM 65%):
//  - unroll 8 with manual load-batching: 8 independent LDG.128 in flight
//    per thread -> 56KB in-flight/SM (was 28KB, Little's-law floor ~21KB)
//  - block=64, grid=1024: 7v6 blocks/SM imbalance instead of 2v1
//  - __ldcs/__stcs: streaming data, evict-first, reduce L2 residency

#define T_STEPS 128
#define BN4 65536  // (64*4096)/4 float4 columns

__global__ __launch_bounds__(64) void snn_leaky_kernel(
    const float4* __restrict__ x4, float4* __restrict__ o4)
{
    int idx = blockIdx.x * blockDim.x + threadIdx.x;  // 0..BN4-1

    float4 mem = make_float4(0.f, 0.f, 0.f, 0.f);
    float4 spk = make_float4(0.f, 0.f, 0.f, 0.f);

    const float4* xp = x4 + idx;
    float4* op = o4 + idx;

    for (int t = 0; t < T_STEPS; t += 8) {
        // front-batch 8 independent loads (MLP=8)
        float4 a[8];
#pragma unroll
        for (int u = 0; u < 8; u++)
            a[u] = __ldcs(xp + (t + u) * BN4);

#pragma unroll
        for (int u = 0; u < 8; u++) {
            mem.x = 0.5f * mem.x + a[u].x - spk.x;
            mem.y = 0.5f * mem.y + a[u].y - spk.y;
            mem.z = 0.5f * mem.z + a[u].z - spk.z;
            mem.w = 0.5f * mem.w + a[u].w - spk.w;

            spk.x = (mem.x > 1.0f) ? 1.0f : 0.0f;
            spk.y = (mem.y > 1.0f) ? 1.0f : 0.0f;
            spk.z = (mem.z > 1.0f) ? 1.0f : 0.0f;
            spk.w = (mem.w > 1.0f) ? 1.0f : 0.0f;

            __stcs(op + (t + u) * BN4, spk);
        }
    }
}

extern "C" void kernel_launch(void* const* d_in, const int* in_sizes, int n_in,
                              void* d_out, int out_size)
{
    const float4* x4 = (const float4*)d_in[0];
    float4* o4 = (float4*)d_out;
    snn_leaky_kernel<<<BN4 / 64, 64>>>(x4, o4);
}